// round 10
// baseline (speedup 1.0000x reference)
#include <cuda_runtime.h>
#include <math.h>

// RT-DETR post-processing, two kernels:
//   K12: fused per-(batch,half) CTA: warp-per-query max/argmax over logits,
//        sigmoid+threshold -> score-space u64 keys in smem, bitonic-sort the
//        512 keys DESC, write sorted half to scratch.
//   K2b: bitonic halver (keep top 512) + short merge + emit top-300.
// Output (concat f32): scores[256,300] | labels[256,300] | boxes[256,300,4]

#define NB      256
#define NQ      1000
#define NC      80
#define SORT_N  1024
#define TOPK    300
#define THRESH  0.05f

typedef unsigned long long u64;
typedef unsigned int       u32;

__device__ u64 g_keys[NB * SORT_N];   // 2 MB scratch (sorted halves)

__device__ __forceinline__ u32 f2ord(u32 b) {            // order-preserving f32->u32
    return (b & 0x80000000u) ? ~b : (b | 0x80000000u);
}
__device__ __forceinline__ u32 ord2f(u32 u) {
    return (u & 0x80000000u) ? (u ^ 0x80000000u) : ~u;
}

// ---------------------------------------------------------------------------
// Bitonic helpers (descending only; hybrid register/shfl + smem)
// ---------------------------------------------------------------------------
__device__ __forceinline__ u64 keep_mm(u64 v, u64 pv, bool kmax) {
    return kmax ? (v > pv ? v : pv) : (v < pv ? v : pv);
}

template<int K, int JSTART>
__device__ __forceinline__ void reg_merge(u64 &v0, u64 &v1, int e0, int e1)
{
    #pragma unroll
    for (int j = JSTART; j >= 1; j >>= 1) {
        if (j == 32) {
            bool desc = ((e0 & K) == 0);
            if (desc ? (v0 < v1) : (v0 > v1)) { u64 t = v0; v0 = v1; v1 = t; }
        } else {
            u64 p0 = __shfl_xor_sync(0xffffffffu, v0, j);
            u64 p1 = __shfl_xor_sync(0xffffffffu, v1, j);
            bool desc0 = ((e0 & K) == 0);
            bool desc1 = ((e1 & K) == 0);
            bool low   = ((e0 & j) == 0);
            v0 = keep_mm(v0, p0, desc0 == low);
            v1 = keep_mm(v1, p1, desc1 == low);
        }
    }
}

__device__ __forceinline__ void smem_step(u64* keys, int t, int j, int k)
{
    int i  = ((t & ~(j - 1)) << 1) | (t & (j - 1));
    int ix = i + j;
    u64 a = keys[i];
    u64 c = keys[ix];
    bool desc = ((i & k) == 0);
    if (desc ? (a < c) : (a > c)) { keys[i] = c; keys[ix] = a; }
}

// ---------------------------------------------------------------------------
// K12: grid=512 (b = blk>>1, h = blk&1), block=512 (16 warps).
// Phase A: each warp computes keys for 32 query-slots (4/iter, 8 iters) into
//          smem. Phase B: threads 0..255 sort the 512 keys DESC, write back.
// ---------------------------------------------------------------------------
__global__ __launch_bounds__(512)
void k12_argmax_sort(const float* __restrict__ logits)
{
    __shared__ u64 skeys[512];

    const int b    = blockIdx.x >> 1;
    const int h    = blockIdx.x & 1;
    const int t    = threadIdx.x;
    const int w    = t >> 5;
    const int lane = t & 31;

    const int     base_q = h * 512;
    const float4* lg4    = (const float4*)(logits + (size_t)b * NQ * NC);

    // ---- Phase A: argmax + sigmoid + key build (all 16 warps) ----
    #pragma unroll 1
    for (int it = 0; it < 8; it++) {
        const int slot0 = w * 32 + it * 4;
        const int q0    = base_q + slot0;

        u32 u[4]; int id[4];
        #pragma unroll
        for (int j = 0; j < 4; j++) { u[j] = 0u; id[j] = 1023; }

        if (lane < NC / 4) {                          // 20 data lanes
            #pragma unroll
            for (int j = 0; j < 4; j++) {             // 4 independent LDG.128
                if (q0 + j < NQ) {
                    float4 x = lg4[(q0 + j) * (NC / 4) + lane];
                    float v = x.x; int idx = lane * 4;
                    if (x.y > v) { v = x.y; idx = lane * 4 + 1; }
                    if (x.z > v) { v = x.z; idx = lane * 4 + 2; }
                    if (x.w > v) { v = x.w; idx = lane * 4 + 3; }
                    u[j]  = f2ord(__float_as_uint(v));
                    id[j] = idx;
                }
            }
        }

        u32 m[4], am[4];
        #pragma unroll
        for (int j = 0; j < 4; j++) {
            m[j] = __reduce_max_sync(0xffffffffu, u[j]);
            u32 cand = (u[j] == m[j]) ? (u32)id[j] : 1023u;  // ties -> low class
            am[j] = __reduce_min_sync(0xffffffffu, cand);
        }

        if (lane < 4) {       // lane j finalizes query q0+j
            u32 mm = (lane == 0) ? m[0]  : (lane == 1) ? m[1]  : (lane == 2) ? m[2]  : m[3];
            u32 aa = (lane == 0) ? am[0] : (lane == 1) ? am[1] : (lane == 2) ? am[2] : am[3];
            int q = q0 + lane;
            u64 key = 0ull;                            // padding: below all real
            if (q < NQ) {
                float v     = __uint_as_float(ord2f(mm));
                float score = 1.0f / (1.0f + expf(-v));
                float ms    = (score > THRESH) ? score : -1.0f;
                u32 sbits   = f2ord(__float_as_uint(ms));
                // [score 32b | (0xFFFF - q) 16b (ties -> lower q) | label 16b]
                key = ((u64)sbits << 32)
                    | ((u64)(u32)(0xFFFF - q) << 16)
                    | (u64)aa;
            }
            skeys[slot0 + lane] = key;
        }
    }
    __syncthreads();

    // ---- Phase B: sort 512 DESC (threads 0..255; others just hit barriers) ----
    const bool s  = (t < 256);
    const int  e0 = 64 * (t >> 5) + lane;    // valid for t<256 (w 0..7)
    const int  e1 = e0 + 32;
    u64 v0 = 0, v1 = 0;

    if (s) {
        v0 = skeys[e0]; v1 = skeys[e1];
        reg_merge<2,  1 >(v0, v1, e0, e1);
        reg_merge<4,  2 >(v0, v1, e0, e1);
        reg_merge<8,  4 >(v0, v1, e0, e1);
        reg_merge<16, 8 >(v0, v1, e0, e1);
        reg_merge<32, 16>(v0, v1, e0, e1);
        reg_merge<64, 32>(v0, v1, e0, e1);
        skeys[e0] = v0; skeys[e1] = v1;
    }
    __syncthreads();

    if (s) smem_step(skeys, t, 64, 128);
    __syncthreads();
    if (s) {
        v0 = skeys[e0]; v1 = skeys[e1];
        reg_merge<128, 32>(v0, v1, e0, e1);
        skeys[e0] = v0; skeys[e1] = v1;
    }
    __syncthreads();

    if (s) smem_step(skeys, t, 128, 256);
    __syncthreads();
    if (s) smem_step(skeys, t,  64, 256);
    __syncthreads();
    if (s) {
        v0 = skeys[e0]; v1 = skeys[e1];
        reg_merge<256, 32>(v0, v1, e0, e1);
        skeys[e0] = v0; skeys[e1] = v1;
    }
    __syncthreads();

    if (s) smem_step(skeys, t, 256, 512);
    __syncthreads();
    if (s) smem_step(skeys, t, 128, 512);
    __syncthreads();
    if (s) smem_step(skeys, t,  64, 512);
    __syncthreads();
    if (s) {
        v0 = skeys[e0]; v1 = skeys[e1];
        reg_merge<512, 32>(v0, v1, e0, e1);
        // fully sorted descending -> scratch for the merge kernel
        u64* gk = g_keys + (size_t)b * SORT_N + h * 512;
        gk[e0] = v0; gk[e1] = v1;
    }
}

// ---------------------------------------------------------------------------
// K2b: grid=256, block=256. Halver keeps top 512 (bitonic), merge, emit 300.
// ---------------------------------------------------------------------------
__device__ __forceinline__ void emit_one(u64 key, int e, int b,
                                         float img_w, float img_h,
                                         const float* __restrict__ boxes,
                                         float* __restrict__ out)
{
    const int S = NB * TOPK;
    u32 u    = (u32)(key >> 32);
    float ms = __uint_as_float(ord2f(u));
    int q    = 0xFFFF - (int)((key >> 16) & 0xFFFFu);
    int lab  = (int)(key & 0xFFFFu);
    bool valid = ms > THRESH;

    int o = b * TOPK + e;
    out[o]     = valid ? ms : 0.0f;
    out[S + o] = valid ? (float)lab : -1.0f;

    float4 bx = ((const float4*)boxes)[(size_t)b * NQ + q];
    float x0 = (bx.x - 0.5f * bx.z) * img_w;
    float y0 = (bx.y - 0.5f * bx.w) * img_h;
    float x1 = (bx.x + 0.5f * bx.z) * img_w;
    float y1 = (bx.y + 0.5f * bx.w) * img_h;
    ((float4*)(out + 2 * S))[o] = valid ? make_float4(x0, y0, x1, y1)
                                        : make_float4(0.f, 0.f, 0.f, 0.f);
}

__global__ __launch_bounds__(256)
void k2b_merge_emit(const float* __restrict__ boxes,
                    const float* __restrict__ tsizes,
                    float* __restrict__ out)
{
    __shared__ u64 keys[512];

    const int b = blockIdx.x;
    const int t = threadIdx.x;
    const int w = t >> 5;
    const int l = t & 31;
    const int e0 = 64 * w + l;     // 0..511
    const int e1 = e0 + 32;

    const u64* gk = g_keys + (size_t)b * SORT_N;

    // Halver: both halves sorted DESC; C[i] = max(A[i], B[511-i]) holds the
    // 512 largest keys and is bitonic. Bottom half never touched again.
    {
        u64 a0 = gk[t];         u64 b0 = gk[1023 - t];
        u64 a1 = gk[t + 256];   u64 b1 = gk[767  - t];
        keys[t]       = (a0 > b0) ? a0 : b0;
        keys[t + 256] = (a1 > b1) ? a1 : b1;
    }
    __syncthreads();

    // Bitonic merge of 512, descending (k=512 => all desc)
    smem_step(keys, t, 256, 512); __syncthreads();
    smem_step(keys, t, 128, 512); __syncthreads();
    smem_step(keys, t,  64, 512); __syncthreads();

    u64 v0 = keys[e0], v1 = keys[e1];
    reg_merge<1024, 32>(v0, v1, e0, e1);   // K>511 => all desc

    const float img_h = tsizes[2 * b + 0];
    const float img_w = tsizes[2 * b + 1];
    if (e0 < TOPK) emit_one(v0, e0, b, img_w, img_h, boxes, out);
    if (e1 < TOPK) emit_one(v1, e1, b, img_w, img_h, boxes, out);
}

// ---------------------------------------------------------------------------
extern "C" void kernel_launch(void* const* d_in, const int* in_sizes, int n_in,
                              void* d_out, int out_size)
{
    const float* logits = (const float*)d_in[0];   // (256,1000,80) f32
    const float* boxes  = (const float*)d_in[1];   // (256,1000,4)  f32
    const float* tsizes = (const float*)d_in[2];   // (256,2)       f32
    float* out = (float*)d_out;                    // 460800 f32

    k12_argmax_sort<<<512, 512>>>(logits);
    k2b_merge_emit<<<NB, 256>>>(boxes, tsizes, out);
}

// round 11
// speedup vs baseline: 1.2117x; 1.2117x over previous
#include <cuda_runtime.h>
#include <math.h>

// RT-DETR post-processing, two kernels:
//   K1 : per-query max/argmax over logits (no sigmoid) -> raw u64 keys (8000 CTAs)
//   K2 : one 512-thread CTA per batch: cp.async box table to smem, convert keys
//        to score space, sort both 512-halves DESC concurrently (warpgroup per
//        half), in-smem bitonic halver (top 512) + merge + emit top-300.
// Output (concat f32): scores[256,300] | labels[256,300] | boxes[256,300,4]

#define NB      256
#define NQ      1000
#define NC      80
#define SORT_N  1024
#define TOPK    300
#define THRESH  0.05f

typedef unsigned long long u64;
typedef unsigned int       u32;

__device__ u64 g_keys[NB * SORT_N];   // 2 MB scratch (raw keys, k1 -> k2)

__device__ __forceinline__ u32 f2ord(u32 b) {            // order-preserving f32->u32
    return (b & 0x80000000u) ? ~b : (b | 0x80000000u);
}
__device__ __forceinline__ u32 ord2f(u32 u) {
    return (u & 0x80000000u) ? (u ^ 0x80000000u) : ~u;
}

// ---------------------------------------------------------------------------
// K1: grid=8000, block=256 (8 warps); each warp handles 4 consecutive queries.
// (R9 shape, measured 17.0us @ 62% DRAM.)
// ---------------------------------------------------------------------------
__global__ __launch_bounds__(256)
void k1_argmax(const float* __restrict__ logits)
{
    const int warp = threadIdx.x >> 5;
    const int lane = threadIdx.x & 31;
    const int f0   = (blockIdx.x * 8 + warp) * 4;     // first flat query (b*NQ+q)

    const float4* base = (const float4*)logits + (size_t)f0 * (NC / 4);

    u32 u[4]; int id[4];
    #pragma unroll
    for (int j = 0; j < 4; j++) { u[j] = 0u; id[j] = 1023; }

    if (lane < NC / 4) {                              // 20 lanes carry data
        #pragma unroll
        for (int j = 0; j < 4; j++) {                 // 4 independent LDG.128
            float4 x = base[j * (NC / 4) + lane];
            float v = x.x; int idx = lane * 4;
            if (x.y > v) { v = x.y; idx = lane * 4 + 1; }
            if (x.z > v) { v = x.z; idx = lane * 4 + 2; }
            if (x.w > v) { v = x.w; idx = lane * 4 + 3; }
            u[j]  = f2ord(__float_as_uint(v));
            id[j] = idx;
        }
    }

    u32 m[4], am[4];
    #pragma unroll
    for (int j = 0; j < 4; j++) {
        m[j] = __reduce_max_sync(0xffffffffu, u[j]);
        u32 cand = (u[j] == m[j]) ? (u32)id[j] : 1023u;   // ties -> lowest class
        am[j] = __reduce_min_sync(0xffffffffu, cand);
    }

    if (lane < 4) {   // lanes 0..3 finalize one query each (coalesced 32B store)
        u32 mm = (lane == 0) ? m[0]  : (lane == 1) ? m[1]  : (lane == 2) ? m[2]  : m[3];
        u32 aa = (lane == 0) ? am[0] : (lane == 1) ? am[1] : (lane == 2) ? am[2] : am[3];
        int f = f0 + lane;
        int b = f / NQ;
        int q = f - b * NQ;
        g_keys[b * SORT_N + q] = ((u64)mm << 32)
                               | ((u64)(u32)(0xFFFF - q) << 16)
                               | (u64)aa;
    }
}

// ---------------------------------------------------------------------------
// cp.async helpers
// ---------------------------------------------------------------------------
__device__ __forceinline__ u32 smem_u32(const void* p) {
    u32 a;
    asm("{ .reg .u64 t; cvta.to.shared.u64 t, %1; cvt.u32.u64 %0, t; }"
        : "=r"(a) : "l"(p));
    return a;
}
__device__ __forceinline__ void cp_async16(u32 saddr, const void* gptr) {
    asm volatile("cp.async.cg.shared.global [%0], [%1], 16;"
                 :: "r"(saddr), "l"(gptr) : "memory");
}
#define CP_ASYNC_COMMIT() asm volatile("cp.async.commit_group;" ::: "memory")
#define CP_ASYNC_WAIT0()  asm volatile("cp.async.wait_group 0;"  ::: "memory")

// ---------------------------------------------------------------------------
// Bitonic helpers (descending only; hybrid register/shfl + smem)
// ---------------------------------------------------------------------------
__device__ __forceinline__ u64 keep_mm(u64 v, u64 pv, bool kmax) {
    return kmax ? (v > pv ? v : pv) : (v < pv ? v : pv);
}

template<int K, int JSTART>
__device__ __forceinline__ void reg_merge(u64 &v0, u64 &v1, int e0, int e1)
{
    #pragma unroll
    for (int j = JSTART; j >= 1; j >>= 1) {
        if (j == 32) {
            bool desc = ((e0 & K) == 0);
            if (desc ? (v0 < v1) : (v0 > v1)) { u64 t = v0; v0 = v1; v1 = t; }
        } else {
            u64 p0 = __shfl_xor_sync(0xffffffffu, v0, j);
            u64 p1 = __shfl_xor_sync(0xffffffffu, v1, j);
            bool desc0 = ((e0 & K) == 0);
            bool desc1 = ((e1 & K) == 0);
            bool low   = ((e0 & j) == 0);
            v0 = keep_mm(v0, p0, desc0 == low);
            v1 = keep_mm(v1, p1, desc1 == low);
        }
    }
}

__device__ __forceinline__ void smem_step(u64* keys, int t, int j, int k)
{
    int i  = ((t & ~(j - 1)) << 1) | (t & (j - 1));
    int ix = i + j;
    u64 a = keys[i];
    u64 c = keys[ix];
    bool desc = ((i & k) == 0);
    if (desc ? (a < c) : (a > c)) { keys[i] = c; keys[ix] = a; }
}

// Convert raw [ord(logit)|q|label] key to score-space key. Bit-identical to
// applying sigmoid/threshold/f2ord before packing.
__device__ __forceinline__ u64 convert_key(u64 raw)
{
    u32 mo = (u32)(raw >> 32);
    float v     = __uint_as_float(ord2f(mo));
    float score = 1.0f / (1.0f + expf(-v));
    float ms    = (score > THRESH) ? score : -1.0f;
    u32 sb = f2ord(__float_as_uint(ms));
    return ((u64)sb << 32) | (raw & 0xFFFFFFFFull);
}

// ---------------------------------------------------------------------------
// K2: grid=256, block=512 (two 256-thread sort groups).
// ---------------------------------------------------------------------------
__global__ __launch_bounds__(512)
void k2_sort_merge_emit(const float* __restrict__ boxes,
                        const float* __restrict__ tsizes,
                        float* __restrict__ out)
{
    __shared__ u64    keys[SORT_N];     //  8 KB
    __shared__ float4 sboxes[NQ];       // 16 KB

    const int b = blockIdx.x;
    const int t = threadIdx.x;

    // ---- prefetch the batch's box table into smem (fire-and-forget) ----
    {
        const float4* gb = (const float4*)boxes + (size_t)b * NQ;
        u32 sb_base = smem_u32(sboxes);
        for (int i = t; i < NQ; i += 512)
            cp_async16(sb_base + (u32)i * 16u, gb + i);
        CP_ASYNC_COMMIT();
    }

    // ---- dual 512-sort: warpgroup g sorts half g (both concurrently) ----
    const int g  = t >> 8;          // half / warpgroup
    const int tt = t & 255;         // local thread within group
    const int l  = t & 31;
    const int wl = tt >> 5;
    const int e0 = 64 * wl + l;     // local element ids within the half
    const int e1 = e0 + 32;

    u64*       hk = keys + g * 512;
    const u64* gk = g_keys + (size_t)b * SORT_N + g * 512;

    u64 v0 = (g * 512 + e0 < NQ) ? convert_key(gk[e0]) : 0ull;
    u64 v1 = (g * 512 + e1 < NQ) ? convert_key(gk[e1]) : 0ull;

    reg_merge<2,  1 >(v0, v1, e0, e1);
    reg_merge<4,  2 >(v0, v1, e0, e1);
    reg_merge<8,  4 >(v0, v1, e0, e1);
    reg_merge<16, 8 >(v0, v1, e0, e1);
    reg_merge<32, 16>(v0, v1, e0, e1);
    reg_merge<64, 32>(v0, v1, e0, e1);
    hk[e0] = v0; hk[e1] = v1;
    __syncthreads();

    smem_step(hk, tt, 64, 128);  __syncthreads();
    v0 = hk[e0]; v1 = hk[e1];
    reg_merge<128, 32>(v0, v1, e0, e1);
    hk[e0] = v0; hk[e1] = v1;
    __syncthreads();

    smem_step(hk, tt, 128, 256); __syncthreads();
    smem_step(hk, tt,  64, 256); __syncthreads();
    v0 = hk[e0]; v1 = hk[e1];
    reg_merge<256, 32>(v0, v1, e0, e1);
    hk[e0] = v0; hk[e1] = v1;
    __syncthreads();

    smem_step(hk, tt, 256, 512); __syncthreads();
    smem_step(hk, tt, 128, 512); __syncthreads();
    smem_step(hk, tt,  64, 512); __syncthreads();
    v0 = hk[e0]; v1 = hk[e1];
    reg_merge<512, 32>(v0, v1, e0, e1);
    hk[e0] = v0; hk[e1] = v1;
    __syncthreads();

    // ---- halver: C[i] = max(A[i], B[511-i]) keeps the 512 largest (bitonic)
    const bool s = (t < 256);
    {
        u64 a0 = 0, b0 = 0, a1 = 0, b1 = 0;
        if (s) {
            a0 = keys[t];       b0 = keys[1023 - t];
            a1 = keys[t + 256]; b1 = keys[767  - t];
        }
        __syncthreads();
        if (s) {
            keys[t]       = (a0 > b0) ? a0 : b0;
            keys[t + 256] = (a1 > b1) ? a1 : b1;
        }
        CP_ASYNC_WAIT0();            // box table definitely resident by now
        __syncthreads();
    }

    // ---- bitonic merge of 512 descending ----
    if (s) smem_step(keys, t, 256, 512);
    __syncthreads();
    if (s) smem_step(keys, t, 128, 512);
    __syncthreads();
    if (s) smem_step(keys, t,  64, 512);
    __syncthreads();

    if (s) {
        u64 m0 = keys[e0], m1 = keys[e1];      // for t<256: e0 == 64*(t>>5)+l
        reg_merge<1024, 32>(m0, m1, e0, e1);   // K>511 => all desc

        const float img_h = tsizes[2 * b + 0];
        const float img_w = tsizes[2 * b + 1];
        const int   S     = NB * TOPK;

        #pragma unroll
        for (int r = 0; r < 2; r++) {
            u64 key = r ? m1 : m0;
            int e   = r ? e1 : e0;
            if (e < TOPK) {
                u32 uu   = (u32)(key >> 32);
                float ms = __uint_as_float(ord2f(uu));
                int q    = 0xFFFF - (int)((key >> 16) & 0xFFFFu);
                int lab  = (int)(key & 0xFFFFu);
                bool valid = ms > THRESH;

                int o = b * TOPK + e;
                out[o]     = valid ? ms : 0.0f;
                out[S + o] = valid ? (float)lab : -1.0f;

                float4 bx = sboxes[q];
                float x0 = (bx.x - 0.5f * bx.z) * img_w;
                float y0 = (bx.y - 0.5f * bx.w) * img_h;
                float x1 = (bx.x + 0.5f * bx.z) * img_w;
                float y1 = (bx.y + 0.5f * bx.w) * img_h;
                ((float4*)(out + 2 * S))[o] =
                    valid ? make_float4(x0, y0, x1, y1)
                          : make_float4(0.f, 0.f, 0.f, 0.f);
            }
        }
    }
}

// ---------------------------------------------------------------------------
extern "C" void kernel_launch(void* const* d_in, const int* in_sizes, int n_in,
                              void* d_out, int out_size)
{
    const float* logits = (const float*)d_in[0];   // (256,1000,80) f32
    const float* boxes  = (const float*)d_in[1];   // (256,1000,4)  f32
    const float* tsizes = (const float*)d_in[2];   // (256,2)       f32
    float* out = (float*)d_out;                    // 460800 f32

    k1_argmax<<<8000, 256>>>(logits);
    k2_sort_merge_emit<<<NB, 512>>>(boxes, tsizes, out);
}